// round 13
// baseline (speedup 1.0000x reference)
#include <cuda_runtime.h>
#include <cuda_bf16.h>
#include <cstdint>

// Problem constants
#define B_   64
#define L_   256
#define D_   768
#define C_   200
#define WLD  2304
#define PE_ROWS 513
#define CE_ROWS 201

// GEMM tiling
#define BM 128
#define BN 128
#define BK 32
#define KT 24                  // 768/32
#define P32 36                 // smem row pitch in 32-bit words (144 B)
#define NBLK_MAIN 128
#define NBLK_PE   5
#define NBLK_CE   2

// smem word offsets (tile = 128 rows * 36 words = 4608 words = 18432 B)
#define AW0 0
#define BW0 4608
#define AW1 9216
#define BW1 13824
#define SMEM_TOT 73728

// Scratch (device globals — no allocation allowed)
__device__ float g_SW [B_ * L_ * C_];
__device__ float g_PEW[PE_ROWS * C_];
__device__ float g_CEW[CE_ROWS * C_];
// W prepacked as tf32 smem tile images: [seg(3)][cblk(2)][kt(24)], 128 x P32 words
__device__ __align__(16) uint32_t g_Wimg32[3 * 2 * KT * 128 * P32];   // ~2.65 MB

// ---------------- helpers ----------------
__device__ __forceinline__ uint32_t smem_u32(const void* p) {
    uint32_t a;
    asm("{ .reg .u64 t; cvta.to.shared.u64 t, %1; cvt.u32.u64 %0, t; }" : "=r"(a) : "l"(p));
    return a;
}
__device__ __forceinline__ uint32_t f2tf32(float x) {
    uint32_t r;
    asm("cvt.rna.tf32.f32 %0, %1;" : "=r"(r) : "f"(x));
    return r;
}
__device__ __forceinline__ void mma_tf32(float* d, const uint32_t* a, const uint32_t* b) {
    asm volatile(
        "mma.sync.aligned.m16n8k8.row.col.f32.tf32.tf32.f32 "
        "{%0,%1,%2,%3}, {%4,%5,%6,%7}, {%8,%9}, {%0,%1,%2,%3};\n"
        : "+f"(d[0]), "+f"(d[1]), "+f"(d[2]), "+f"(d[3])
        : "r"(a[0]), "r"(a[1]), "r"(a[2]), "r"(a[3]), "r"(b[0]), "r"(b[1]));
}
#define CP_ASYNC16(dst, src) \
    asm volatile("cp.async.cg.shared.global [%0], [%1], 16;" :: "r"(dst), "l"(src))
#define CP_COMMIT()  asm volatile("cp.async.commit_group;" ::: "memory")
#define CP_WAIT0()   asm volatile("cp.async.wait_group 0;" ::: "memory")

// ---------------- prepack W -> tf32 smem-image tiles ----------------
// 144 images x 1024 16B-units, 1 unit per thread (grid 576 x 256) for TLP
__global__ __launch_bounds__(256) void prepack_W(const float* __restrict__ W) {
    const int u     = blockIdx.x * 256 + threadIdx.x;   // 0..147455
    const int image = u >> 10;
    const int rem   = u & 1023;
    const int row   = rem >> 3;                  // 0..127
    const int c4    = rem & 7;

    const int seg  = image / (2 * KT);
    const int rem2 = image % (2 * KT);
    const int cblk = rem2 / KT;
    const int kt   = rem2 % KT;

    const int cls = cblk * 128 + row;
    float4 v = make_float4(0.f, 0.f, 0.f, 0.f);
    if (cls < C_)
        v = *(const float4*)(W + (size_t)cls * WLD + seg * D_ + kt * BK + c4 * 4);

    uint4 o = make_uint4(f2tf32(v.x), f2tf32(v.y), f2tf32(v.z), f2tf32(v.w));
    *(uint4*)(g_Wimg32 + (size_t)image * (128 * P32) + row * P32 + c4 * 4) = o;
}

// ---------------- fused triple GEMM (tf32 mma, 64x64 warp tiles) ----------------
__global__ __launch_bounds__(128, 2) void tfgemm_fused(
    const float* __restrict__ A0,
    const float* __restrict__ A1,
    const float* __restrict__ A2,
    const float* __restrict__ bias,
    float* __restrict__ C0,
    float* __restrict__ C1,
    float* __restrict__ C2)
{
    // segment select
    int bx = blockIdx.x;
    const float* A;
    float* C;
    int M, seg;
    if (bx < NBLK_MAIN)                { A = A0; C = C0; M = B_ * L_; seg = 0; }
    else if (bx < NBLK_MAIN + NBLK_PE) { A = A1; C = C1; M = PE_ROWS; seg = 1; bx -= NBLK_MAIN; }
    else                               { A = A2; C = C2; M = CE_ROWS; seg = 2; bx -= NBLK_MAIN + NBLK_PE; }
    const int m0   = bx * BM;
    const int cblk = blockIdx.y;
    const int c0   = cblk * BN;

    extern __shared__ __align__(16) char smem[];
    uint32_t* SW32 = (uint32_t*)smem;
    const uint32_t sb = smem_u32(smem);

    const int tid  = threadIdx.x;
    const int lane = tid & 31;
    const int wid  = tid >> 5;        // 0..3
    const int warp_m = wid & 1;       // 2 M-warps (64 rows)
    const int warp_n = wid >> 1;      // 2 N-warps (64 cols)
    const int g   = lane >> 2;        // 0..7
    const int tig = lane & 3;         // 0..3

    // N-waste skip: number of 8-col nt tiles this warp needs (warp-uniform, 0..8)
    const int rem_cols = C_ - (c0 + warp_n * 64);
    const int nt_lim = rem_cols <= 0 ? 0 : (rem_cols >= 64 ? 8 : ((rem_cols + 7) >> 3));
    // B staging units actually needed in this block (cblk1 uses 72 of 128 rows)
    const int blim = (c0 == 0) ? 1152 : ((C_ - BN) * 9);   // 16B-units: rows*9

    // A staging geometry: 8 float4 per thread (128 threads cover 128x32 tile)
    const int st_row = tid >> 3;      // 0..15, +16 per i
    const int st_c4  = tid & 7;       // float4 column 0..7

    const uint32_t* wimg = g_Wimg32 + (size_t)((seg * 2 + cblk) * KT) * (128 * P32);

    float acc[4][8][4];
    #pragma unroll
    for (int mt = 0; mt < 4; mt++)
        #pragma unroll
        for (int nt = 0; nt < 8; nt++)
            #pragma unroll
            for (int r = 0; r < 4; r++) acc[mt][nt][r] = 0.f;

    auto stageB = [&](int kt, int bwoff) {
        const uint32_t dstb = sb + (uint32_t)bwoff * 4;
        const char* src = (const char*)(wimg + (size_t)kt * (128 * P32));
        #pragma unroll
        for (int i = 0; i < 9; i++) {
            const int idx = tid + i * 128;
            if (idx < blim)
                CP_ASYNC16(dstb + (uint32_t)idx * 16, src + (size_t)idx * 16);
        }
        CP_COMMIT();
    };
    auto loadA = [&](int kt, float4* av) {
        #pragma unroll
        for (int i = 0; i < 8; i++) {
            const int row = st_row + i * 16;
            av[i] = make_float4(0.f, 0.f, 0.f, 0.f);
            if (m0 + row < M)
                av[i] = *(const float4*)(A + (size_t)(m0 + row) * D_ + kt * BK + st_c4 * 4);
        }
    };
    auto storeA = [&](const float4* av, int awoff) {
        #pragma unroll
        for (int i = 0; i < 8; i++) {
            const int row = st_row + i * 16;
            uint4 o = make_uint4(f2tf32(av[i].x), f2tf32(av[i].y),
                                 f2tf32(av[i].z), f2tf32(av[i].w));
            *(uint4*)(SW32 + awoff + row * P32 + st_c4 * 4) = o;
        }
    };

    // prologue
    float4 av[8];
    stageB(0, BW0);
    loadA(0, av);
    storeA(av, AW0);
    CP_WAIT0();
    __syncthreads();

    #pragma unroll 1
    for (int kt = 0; kt < KT; kt++) {
        const int b = kt & 1;
        const bool more = (kt + 1) < KT;
        if (more) {                    // issue next-tile loads BEFORE compute
            stageB(kt + 1, b ? BW0 : BW1);
            loadA(kt + 1, av);
        }

        const uint32_t* As = SW32 + (b ? AW1 : AW0);
        const uint32_t* Bs = SW32 + (b ? BW1 : BW0);

        #pragma unroll
        for (int ks = 0; ks < 4; ks++) {
            const int k0 = ks * 8 + tig;
            uint32_t bf[8][2];
            #pragma unroll
            for (int nt = 0; nt < 8; nt++) {
                if (nt < nt_lim) {
                    const int naddr = (warp_n * 64 + nt * 8 + g) * P32 + k0;
                    bf[nt][0] = Bs[naddr];
                    bf[nt][1] = Bs[naddr + 4];
                }
            }
            #pragma unroll
            for (int mt = 0; mt < 4; mt++) {
                const int maddr = (warp_m * 64 + mt * 16 + g) * P32 + k0;
                uint32_t a[4];
                a[0] = As[maddr];
                a[1] = As[maddr + 8 * P32];
                a[2] = As[maddr + 4];
                a[3] = As[maddr + 8 * P32 + 4];
                #pragma unroll
                for (int nt = 0; nt < 8; nt++)
                    if (nt < nt_lim)
                        mma_tf32(acc[mt][nt], a, bf[nt]);
            }
        }

        if (more) {
            storeA(av, b ? AW0 : AW1);   // convert+store AFTER compute (latency hidden)
            CP_WAIT0();
            __syncthreads();
        }
    }

    // ---- store (bias folded into CEW segment) ----
    #pragma unroll
    for (int mt = 0; mt < 4; mt++) {
        const int m_g = m0 + warp_m * 64 + mt * 16 + g;
        #pragma unroll
        for (int nt = 0; nt < 8; nt++) {
            const int n_g = c0 + warp_n * 64 + nt * 8 + 2 * tig;
            if (n_g < C_) {
                float b0 = 0.f, b1 = 0.f;
                if (seg == 2) { b0 = bias[n_g]; b1 = bias[n_g + 1]; }
                if (m_g < M)
                    *(float2*)(C + (size_t)m_g * C_ + n_g) =
                        make_float2(acc[mt][nt][0] + b0, acc[mt][nt][1] + b1);
                if (m_g + 8 < M)
                    *(float2*)(C + (size_t)(m_g + 8) * C_ + n_g) =
                        make_float2(acc[mt][nt][2] + b0, acc[mt][nt][3] + b1);
            }
        }
    }
}

// ---------------- gather + add epilogue (2 rows per thread, PROVEN shape) ----------------
__global__ __launch_bounds__(256) void epilogue_kernel(
    const int* __restrict__ head_indexes,
    const int* __restrict__ frame,
    const int* __restrict__ pos,
    float* __restrict__ out)
{
    const int t = threadIdx.x;
    const int lane = t & 63;
    if (lane >= C_ / 4) return;
    const int base = (blockIdx.x << 3) + (t >> 6);   // rows base..base+7, this thread: base, base+4

    #pragma unroll
    for (int h = 0; h < 2; h++) {
        const int r = base + h * 4;
        const int b = r >> 8;
        const int l = r & 255;

        const int hi  = __ldg(&head_indexes[r]);
        const int p   = __ldg(&pos[b]);
        const int rel = l - p + 256;
        const int fk  = (l == p) ? __ldg(&frame[b]) : 0;

        const float4 s = ((const float4*)(g_SW  + ((size_t)b * L_ + hi) * C_))[lane];
        const float4 q = ((const float4*)(g_PEW + (size_t)rel * C_))[lane];
        const float4 f = ((const float4*)(g_CEW + (size_t)fk  * C_))[lane];

        float4 o;
        o.x = s.x + q.x + f.x;
        o.y = s.y + q.y + f.y;
        o.z = s.z + q.z + f.z;
        o.w = s.w + q.w + f.w;
        ((float4*)(out + (size_t)r * C_))[lane] = o;
    }
}

extern "C" void kernel_launch(void* const* d_in, const int* in_sizes, int n_in,
                              void* d_out, int out_size)
{
    const float* seq   = (const float*)d_in[0];
    const float* pe    = (const float*)d_in[1];
    const float* ce    = (const float*)d_in[2];
    const float* W     = (const float*)d_in[3];
    const float* bias  = (const float*)d_in[4];
    const int*   hidx  = (const int*)  d_in[5];
    const int*   frame = (const int*)  d_in[6];
    const int*   pos   = (const int*)  d_in[7];
    float* out = (float*)d_out;

    float *dSW, *dPEW, *dCEW;
    cudaGetSymbolAddress((void**)&dSW,  g_SW);
    cudaGetSymbolAddress((void**)&dPEW, g_PEW);
    cudaGetSymbolAddress((void**)&dCEW, g_CEW);

    static int init_done = 0;
    if (!init_done) {
        cudaFuncSetAttribute(tfgemm_fused,
                             cudaFuncAttributeMaxDynamicSharedMemorySize, SMEM_TOT);
        init_done = 1;
    }

    // 1) prepack W -> tf32 smem tile images (1 unit/thread for TLP)
    prepack_W<<<576, 256>>>(W);

    // 2) fused triple GEMM (64x64 warp tiles, 128 threads)
    dim3 gG(NBLK_MAIN + NBLK_PE + NBLK_CE, 2);   // (135, 2)
    tfgemm_fused<<<gG, 128, SMEM_TOT>>>(seq, pe, ce, bias, dSW, dPEW, dCEW);

    // 3) gather + add epilogue (2-row shape, proven in R6/R11/R12)
    epilogue_kernel<<<(B_ * L_) / 8, 256>>>(hidx, frame, pos, out);
}

// round 14
// speedup vs baseline: 1.1641x; 1.1641x over previous
#include <cuda_runtime.h>
#include <cuda_bf16.h>
#include <cstdint>

// Problem constants
#define B_   64
#define L_   256
#define D_   768
#define C_   200
#define WLD  2304
#define PE_ROWS 513
#define CE_ROWS 201

// GEMM tiling: 128 x 200 block tile (all N in one block)
#define BM 128
#define BK 32
#define KT 24                  // 768/32
#define P32 36                 // smem row pitch in 32-bit words (144 B)
#define NT_TOT 25              // 200/8 n-tiles
#define NBLK_MAIN 128
#define NBLK_PE   5
#define NBLK_CE   2

// smem word offsets: A tile 128*36=4608 w, B tile 200*36=7200 w
#define AW0 0
#define AW1 4608
#define BW0 9216
#define BW1 16416
#define SMEM_TOT 94464         // 23616 words * 4

#define IMG32 7200             // words per B image (200 rows x 36)

// Scratch (device globals — no allocation allowed)
__device__ float g_SW [B_ * L_ * C_];
__device__ float g_PEW[PE_ROWS * C_];
__device__ float g_CEW[CE_ROWS * C_];
// W prepacked as tf32 images: [seg(3)][kt(24)], 200 x P32 words each (~2 MB)
__device__ __align__(16) uint32_t g_Wimg32[3 * KT * IMG32];

// ---------------- helpers ----------------
__device__ __forceinline__ uint32_t smem_u32(const void* p) {
    uint32_t a;
    asm("{ .reg .u64 t; cvta.to.shared.u64 t, %1; cvt.u32.u64 %0, t; }" : "=r"(a) : "l"(p));
    return a;
}
__device__ __forceinline__ uint32_t f2tf32(float x) {
    uint32_t r;
    asm("cvt.rna.tf32.f32 %0, %1;" : "=r"(r) : "f"(x));
    return r;
}
__device__ __forceinline__ void mma_tf32(float* d, const uint32_t* a, const uint32_t* b) {
    asm volatile(
        "mma.sync.aligned.m16n8k8.row.col.f32.tf32.tf32.f32 "
        "{%0,%1,%2,%3}, {%4,%5,%6,%7}, {%8,%9}, {%0,%1,%2,%3};\n"
        : "+f"(d[0]), "+f"(d[1]), "+f"(d[2]), "+f"(d[3])
        : "r"(a[0]), "r"(a[1]), "r"(a[2]), "r"(a[3]), "r"(b[0]), "r"(b[1]));
}
#define CP_ASYNC16(dst, src) \
    asm volatile("cp.async.cg.shared.global [%0], [%1], 16;" :: "r"(dst), "l"(src))
#define CP_COMMIT()  asm volatile("cp.async.commit_group;" ::: "memory")
#define CP_WAIT0()   asm volatile("cp.async.wait_group 0;" ::: "memory")

// ---------------- prepack W -> tf32 smem-image tiles ----------------
// 72 images x 200 rows x 8 data-units = 115200 units; 1 unit/thread (grid 450)
__global__ __launch_bounds__(256) void prepack_W(const float* __restrict__ W) {
    const int u   = blockIdx.x * 256 + threadIdx.x;   // 0..115199
    const int image = u / 1600;        // seg*KT + kt
    const int rem   = u % 1600;
    const int row   = rem >> 3;        // 0..199 (= class, no padding needed)
    const int c4    = rem & 7;

    const int seg = image / KT;
    const int kt  = image % KT;

    float4 v = *(const float4*)(W + (size_t)row * WLD + seg * D_ + kt * BK + c4 * 4);
    uint4 o = make_uint4(f2tf32(v.x), f2tf32(v.y), f2tf32(v.z), f2tf32(v.w));
    *(uint4*)(g_Wimg32 + (size_t)image * IMG32 + row * P32 + c4 * 4) = o;
}

// ---------------- fused triple GEMM (tf32 mma, full-N block tile) ----------------
__global__ __launch_bounds__(256, 1) void tfgemm_fused(
    const float* __restrict__ A0,
    const float* __restrict__ A1,
    const float* __restrict__ A2,
    const float* __restrict__ bias,
    float* __restrict__ C0,
    float* __restrict__ C1,
    float* __restrict__ C2)
{
    // segment select
    int bx = blockIdx.x;
    const float* A;
    float* C;
    int M, seg;
    if (bx < NBLK_MAIN)                { A = A0; C = C0; M = B_ * L_; seg = 0; }
    else if (bx < NBLK_MAIN + NBLK_PE) { A = A1; C = C1; M = PE_ROWS; seg = 1; bx -= NBLK_MAIN; }
    else                               { A = A2; C = C2; M = CE_ROWS; seg = 2; bx -= NBLK_MAIN + NBLK_PE; }
    const int m0 = bx * BM;

    extern __shared__ __align__(16) char smem[];
    uint32_t* SW32 = (uint32_t*)smem;
    const uint32_t sb = smem_u32(smem);

    const int tid  = threadIdx.x;
    const int lane = tid & 31;
    const int wid  = tid >> 5;
    const int warp_m = wid & 1;    // 2 M-warps (64 rows)
    const int warp_n = wid >> 1;   // 4 N-warp columns
    const int g   = lane >> 2;     // 0..7
    const int tig = lane & 3;      // 0..3

    // 25 n-tiles split 7/6/6/6 across warp_n (warp-uniform)
    const int nt0 = (warp_n == 0) ? 0 : 1 + warp_n * 6;   // 0,7,13,19
    const int ntc = (warp_n == 0) ? 7 : 6;

    // A staging geometry (256 threads cover 128x32 tile, 4 float4/thread)
    const int st_row = tid >> 3;   // +32 per i
    const int st_c4  = tid & 7;

    const uint32_t* wimg = g_Wimg32 + (size_t)(seg * KT) * IMG32;

    float acc[4][7][4];
    #pragma unroll
    for (int mt = 0; mt < 4; mt++)
        #pragma unroll
        for (int nt = 0; nt < 7; nt++)
            #pragma unroll
            for (int r = 0; r < 4; r++) acc[mt][nt][r] = 0.f;

    auto stageB = [&](int kt, int bwoff) {
        const uint32_t dstb = sb + (uint32_t)bwoff * 4;
        const char* src = (const char*)(wimg + (size_t)kt * IMG32);
        #pragma unroll
        for (int i = 0; i < 8; i++) {
            const int idx = tid + i * 256;
            if (idx < 1800)
                CP_ASYNC16(dstb + (uint32_t)idx * 16, src + (size_t)idx * 16);
        }
        CP_COMMIT();
    };
    auto loadA = [&](int kt, float4* av) {
        #pragma unroll
        for (int i = 0; i < 4; i++) {
            const int row = st_row + i * 32;
            av[i] = make_float4(0.f, 0.f, 0.f, 0.f);
            if (m0 + row < M)
                av[i] = *(const float4*)(A + (size_t)(m0 + row) * D_ + kt * BK + st_c4 * 4);
        }
    };
    auto storeA = [&](const float4* av, int awoff) {
        #pragma unroll
        for (int i = 0; i < 4; i++) {
            const int row = st_row + i * 32;
            uint4 o = make_uint4(f2tf32(av[i].x), f2tf32(av[i].y),
                                 f2tf32(av[i].z), f2tf32(av[i].w));
            *(uint4*)(SW32 + awoff + row * P32 + st_c4 * 4) = o;
        }
    };

    // prologue
    float4 av[4];
    stageB(0, BW0);
    loadA(0, av);
    storeA(av, AW0);
    CP_WAIT0();
    __syncthreads();

    #pragma unroll 1
    for (int kt = 0; kt < KT; kt++) {
        const int b = kt & 1;
        const bool more = (kt + 1) < KT;
        if (more) {                    // issue next-tile loads BEFORE compute
            stageB(kt + 1, b ? BW0 : BW1);
            loadA(kt + 1, av);
        }

        const uint32_t* As = SW32 + (b ? AW1 : AW0);
        const uint32_t* Bs = SW32 + (b ? BW1 : BW0);

        #pragma unroll
        for (int ks = 0; ks < 4; ks++) {
            const int k0 = ks * 8 + tig;
            uint32_t bf[7][2];
            #pragma unroll
            for (int nt = 0; nt < 7; nt++) {
                if (nt < ntc) {
                    const int naddr = ((nt0 + nt) * 8 + g) * P32 + k0;
                    bf[nt][0] = Bs[naddr];
                    bf[nt][1] = Bs[naddr + 4];
                }
            }
            #pragma unroll
            for (int mt = 0; mt < 4; mt++) {
                const int maddr = (warp_m * 64 + mt * 16 + g) * P32 + k0;
                uint32_t a[4];
                a[0] = As[maddr];
                a[1] = As[maddr + 8 * P32];
                a[2] = As[maddr + 4];
                a[3] = As[maddr + 8 * P32 + 4];
                #pragma unroll
                for (int nt = 0; nt < 7; nt++)
                    if (nt < ntc)
                        mma_tf32(acc[mt][nt], a, bf[nt]);
            }
        }

        if (more) {
            storeA(av, b ? AW0 : AW1);   // convert+store AFTER compute (latency hidden)
            CP_WAIT0();
            __syncthreads();
        }
    }

    // ---- store (bias folded into CEW segment) ----
    #pragma unroll
    for (int mt = 0; mt < 4; mt++) {
        const int m_g = m0 + warp_m * 64 + mt * 16 + g;
        #pragma unroll
        for (int nt = 0; nt < 7; nt++) {
            if (nt < ntc) {
                const int n_g = (nt0 + nt) * 8 + 2 * tig;
                if (n_g < C_) {
                    float b0 = 0.f, b1 = 0.f;
                    if (seg == 2) { b0 = bias[n_g]; b1 = bias[n_g + 1]; }
                    if (m_g < M)
                        *(float2*)(C + (size_t)m_g * C_ + n_g) =
                            make_float2(acc[mt][nt][0] + b0, acc[mt][nt][1] + b1);
                    if (m_g + 8 < M)
                        *(float2*)(C + (size_t)(m_g + 8) * C_ + n_g) =
                            make_float2(acc[mt][nt][2] + b0, acc[mt][nt][3] + b1);
                }
            }
        }
    }
}

// ---------------- gather + add epilogue (2 rows per thread, PROVEN shape) ----------------
__global__ __launch_bounds__(256) void epilogue_kernel(
    const int* __restrict__ head_indexes,
    const int* __restrict__ frame,
    const int* __restrict__ pos,
    float* __restrict__ out)
{
    const int t = threadIdx.x;
    const int lane = t & 63;
    if (lane >= C_ / 4) return;
    const int base = (blockIdx.x << 3) + (t >> 6);   // rows base..base+7, this thread: base, base+4

    #pragma unroll
    for (int h = 0; h < 2; h++) {
        const int r = base + h * 4;
        const int b = r >> 8;
        const int l = r & 255;

        const int hi  = __ldg(&head_indexes[r]);
        const int p   = __ldg(&pos[b]);
        const int rel = l - p + 256;
        const int fk  = (l == p) ? __ldg(&frame[b]) : 0;

        const float4 s = ((const float4*)(g_SW  + ((size_t)b * L_ + hi) * C_))[lane];
        const float4 q = ((const float4*)(g_PEW + (size_t)rel * C_))[lane];
        const float4 f = ((const float4*)(g_CEW + (size_t)fk  * C_))[lane];

        float4 o;
        o.x = s.x + q.x + f.x;
        o.y = s.y + q.y + f.y;
        o.z = s.z + q.z + f.z;
        o.w = s.w + q.w + f.w;
        ((float4*)(out + (size_t)r * C_))[lane] = o;
    }
}

extern "C" void kernel_launch(void* const* d_in, const int* in_sizes, int n_in,
                              void* d_out, int out_size)
{
    const float* seq   = (const float*)d_in[0];
    const float* pe    = (const float*)d_in[1];
    const float* ce    = (const float*)d_in[2];
    const float* W     = (const float*)d_in[3];
    const float* bias  = (const float*)d_in[4];
    const int*   hidx  = (const int*)  d_in[5];
    const int*   frame = (const int*)  d_in[6];
    const int*   pos   = (const int*)  d_in[7];
    float* out = (float*)d_out;

    float *dSW, *dPEW, *dCEW;
    cudaGetSymbolAddress((void**)&dSW,  g_SW);
    cudaGetSymbolAddress((void**)&dPEW, g_PEW);
    cudaGetSymbolAddress((void**)&dCEW, g_CEW);

    static int init_done = 0;
    if (!init_done) {
        cudaFuncSetAttribute(tfgemm_fused,
                             cudaFuncAttributeMaxDynamicSharedMemorySize, SMEM_TOT);
        init_done = 1;
    }

    // 1) prepack W -> tf32 smem tile images (no cblk duplication)
    prepack_W<<<450, 256>>>(W);

    // 2) fused triple GEMM: full-N block tile, single wave of 135 CTAs
    tfgemm_fused<<<NBLK_MAIN + NBLK_PE + NBLK_CE, 256, SMEM_TOT>>>(
        seq, pe, ce, bias, dSW, dPEW, dCEW);

    // 3) gather + add epilogue (2-row shape, proven)
    epilogue_kernel<<<(B_ * L_) / 8, 256>>>(hidx, frame, pos, out);
}

// round 15
// speedup vs baseline: 1.2164x; 1.0450x over previous
#include <cuda_runtime.h>
#include <cuda_bf16.h>
#include <cstdint>

// Problem constants
#define B_   64
#define L_   256
#define D_   768
#define C_   200
#define WLD  2304
#define PE_ROWS 513
#define CE_ROWS 201

// GEMM tiling: 128 x 200 block tile, BK=64
#define BM 128
#define BK 64
#define KT 12                  // 768/64
#define P32 68                 // smem row pitch in 32-bit words (272 B; 68g%32==4g -> conflict-free)
#define NBLK_MAIN 128
#define NBLK_PE   5
#define NBLK_CE   2

// smem word offsets: A tile 128*68=8704 w, B tile 200*68=13600 w
#define AW0 0
#define AW1 8704
#define BW0 17408
#define BW1 31008
#define SMEM_TOT 178432        // 44608 words * 4

#define IMG32 13600            // words per B image (200 rows x 68, incl pad)

// Scratch (device globals — no allocation allowed)
__device__ float g_SW [B_ * L_ * C_];
__device__ float g_PEW[PE_ROWS * C_];
__device__ float g_CEW[CE_ROWS * C_];
// W prepacked as tf32 images: [seg(3)][kt(12)], 200 x P32 words each (~1.96 MB)
__device__ __align__(16) uint32_t g_Wimg32[3 * KT * IMG32];

// ---------------- helpers ----------------
__device__ __forceinline__ uint32_t smem_u32(const void* p) {
    uint32_t a;
    asm("{ .reg .u64 t; cvta.to.shared.u64 t, %1; cvt.u32.u64 %0, t; }" : "=r"(a) : "l"(p));
    return a;
}
__device__ __forceinline__ uint32_t f2tf32(float x) {
    uint32_t r;
    asm("cvt.rna.tf32.f32 %0, %1;" : "=r"(r) : "f"(x));
    return r;
}
__device__ __forceinline__ void mma_tf32(float* d, const uint32_t* a, const uint32_t* b) {
    asm volatile(
        "mma.sync.aligned.m16n8k8.row.col.f32.tf32.tf32.f32 "
        "{%0,%1,%2,%3}, {%4,%5,%6,%7}, {%8,%9}, {%0,%1,%2,%3};\n"
        : "+f"(d[0]), "+f"(d[1]), "+f"(d[2]), "+f"(d[3])
        : "r"(a[0]), "r"(a[1]), "r"(a[2]), "r"(a[3]), "r"(b[0]), "r"(b[1]));
}
#define CP_ASYNC16(dst, src) \
    asm volatile("cp.async.cg.shared.global [%0], [%1], 16;" :: "r"(dst), "l"(src))
#define CP_COMMIT()  asm volatile("cp.async.commit_group;" ::: "memory")
#define CP_WAIT0()   asm volatile("cp.async.wait_group 0;" ::: "memory")

// ---------------- prepack W -> tf32 smem-image tiles ----------------
// 36 images x 200 rows x 16 data-units = 115200 units; 1 unit/thread (grid 450)
__global__ __launch_bounds__(256) void prepack_W(const float* __restrict__ W) {
    const int u     = blockIdx.x * 256 + threadIdx.x;   // 0..115199
    const int image = u / 3200;        // seg*KT + kt
    const int rem   = u % 3200;
    const int row   = rem >> 4;        // 0..199 (= class)
    const int c4    = rem & 15;        // float4 within 64-col k chunk

    const int seg = image / KT;
    const int kt  = image % KT;

    float4 v = *(const float4*)(W + (size_t)row * WLD + seg * D_ + kt * BK + c4 * 4);
    uint4 o = make_uint4(f2tf32(v.x), f2tf32(v.y), f2tf32(v.z), f2tf32(v.w));
    *(uint4*)(g_Wimg32 + (size_t)image * IMG32 + row * P32 + c4 * 4) = o;
}

// ---------------- fused triple GEMM (tf32 mma, full-N block tile, BK=64) ----------------
__global__ __launch_bounds__(256, 1) void tfgemm_fused(
    const float* __restrict__ A0,
    const float* __restrict__ A1,
    const float* __restrict__ A2,
    const float* __restrict__ bias,
    float* __restrict__ C0,
    float* __restrict__ C1,
    float* __restrict__ C2)
{
    // segment select
    int bx = blockIdx.x;
    const float* A;
    float* C;
    int M, seg;
    if (bx < NBLK_MAIN)                { A = A0; C = C0; M = B_ * L_; seg = 0; }
    else if (bx < NBLK_MAIN + NBLK_PE) { A = A1; C = C1; M = PE_ROWS; seg = 1; bx -= NBLK_MAIN; }
    else                               { A = A2; C = C2; M = CE_ROWS; seg = 2; bx -= NBLK_MAIN + NBLK_PE; }
    const int m0 = bx * BM;

    extern __shared__ __align__(16) char smem[];
    uint32_t* SW32 = (uint32_t*)smem;
    const uint32_t sb = smem_u32(smem);

    const int tid  = threadIdx.x;
    const int lane = tid & 31;
    const int wid  = tid >> 5;
    const int warp_m = wid & 3;    // 4 M-warps (32 rows each) — also the SMSP id
    const int warp_n = wid >> 2;   // 2 N-warp columns
    const int g   = lane >> 2;     // 0..7
    const int tig = lane & 3;      // 0..3

    // 25 n-tiles split 13/12 across warp_n (warp-uniform); SMSPs perfectly balanced (26+24)
    const int nt0 = (warp_n == 0) ? 0 : 13;
    const int ntc = (warp_n == 0) ? 13 : 12;

    // A staging geometry (256 threads cover 128x64 tile, 8 float4/thread)
    const int st_row = tid >> 4;   // 0..15, +16 per i
    const int st_c4  = tid & 15;   // float4 column 0..15

    const uint32_t* wimg = g_Wimg32 + (size_t)(seg * KT) * IMG32;

    float acc[2][13][4];
    #pragma unroll
    for (int mt = 0; mt < 2; mt++)
        #pragma unroll
        for (int nt = 0; nt < 13; nt++)
            #pragma unroll
            for (int r = 0; r < 4; r++) acc[mt][nt][r] = 0.f;

    auto stageB = [&](int kt, int bwoff) {
        const uint32_t dstb = sb + (uint32_t)bwoff * 4;
        const char* src = (const char*)(wimg + (size_t)kt * IMG32);
        #pragma unroll
        for (int i = 0; i < 14; i++) {
            const int idx = tid + i * 256;
            if (idx < 3400)
                CP_ASYNC16(dstb + (uint32_t)idx * 16, src + (size_t)idx * 16);
        }
        CP_COMMIT();
    };
    auto loadA = [&](int kt, float4* av) {
        #pragma unroll
        for (int i = 0; i < 8; i++) {
            const int row = st_row + i * 16;
            av[i] = make_float4(0.f, 0.f, 0.f, 0.f);
            if (m0 + row < M)
                av[i] = *(const float4*)(A + (size_t)(m0 + row) * D_ + kt * BK + st_c4 * 4);
        }
    };
    auto storeA = [&](const float4* av, int awoff) {
        #pragma unroll
        for (int i = 0; i < 8; i++) {
            const int row = st_row + i * 16;
            uint4 o = make_uint4(f2tf32(av[i].x), f2tf32(av[i].y),
                                 f2tf32(av[i].z), f2tf32(av[i].w));
            *(uint4*)(SW32 + awoff + row * P32 + st_c4 * 4) = o;
        }
    };

    // prologue
    float4 av[8];
    stageB(0, BW0);
    loadA(0, av);
    storeA(av, AW0);
    CP_WAIT0();
    __syncthreads();

    #pragma unroll 1
    for (int kt = 0; kt < KT; kt++) {
        const int b = kt & 1;
        const bool more = (kt + 1) < KT;
        if (more) {                    // issue next-tile loads BEFORE compute
            stageB(kt + 1, b ? BW0 : BW1);
            loadA(kt + 1, av);
        }

        const uint32_t* As = SW32 + (b ? AW1 : AW0);
        const uint32_t* Bs = SW32 + (b ? BW1 : BW0);

        #pragma unroll
        for (int ks = 0; ks < 8; ks++) {
            const int k0 = ks * 8 + tig;
            uint32_t bf[13][2];
            #pragma unroll
            for (int nt = 0; nt < 13; nt++) {
                if (nt < ntc) {
                    const int naddr = ((nt0 + nt) * 8 + g) * P32 + k0;
                    bf[nt][0] = Bs[naddr];
                    bf[nt][1] = Bs[naddr + 4];
                }
            }
            #pragma unroll
            for (int mt = 0; mt < 2; mt++) {
                const int maddr = (warp_m * 32 + mt * 16 + g) * P32 + k0;
                uint32_t a[4];
                a[0] = As[maddr];
                a[1] = As[maddr + 8 * P32];
                a[2] = As[maddr + 4];
                a[3] = As[maddr + 8 * P32 + 4];
                #pragma unroll
                for (int nt = 0; nt < 13; nt++)
                    if (nt < ntc)
                        mma_tf32(acc[mt][nt], a, bf[nt]);
            }
        }

        if (more) {
            storeA(av, b ? AW0 : AW1);   // convert+store AFTER compute (latency hidden)
            CP_WAIT0();
            __syncthreads();
        }
    }

    // ---- store (bias folded into CEW segment) ----
    #pragma unroll
    for (int mt = 0; mt < 2; mt++) {
        const int m_g = m0 + warp_m * 32 + mt * 16 + g;
        #pragma unroll
        for (int nt = 0; nt < 13; nt++) {
            if (nt < ntc) {
                const int n_g = (nt0 + nt) * 8 + 2 * tig;
                if (n_g < C_) {
                    float b0 = 0.f, b1 = 0.f;
                    if (seg == 2) { b0 = bias[n_g]; b1 = bias[n_g + 1]; }
                    if (m_g < M)
                        *(float2*)(C + (size_t)m_g * C_ + n_g) =
                            make_float2(acc[mt][nt][0] + b0, acc[mt][nt][1] + b1);
                    if (m_g + 8 < M)
                        *(float2*)(C + (size_t)(m_g + 8) * C_ + n_g) =
                            make_float2(acc[mt][nt][2] + b0, acc[mt][nt][3] + b1);
                }
            }
        }
    }
}

// ---------------- gather + add epilogue (2 rows per thread, PROVEN shape) ----------------
__global__ __launch_bounds__(256) void epilogue_kernel(
    const int* __restrict__ head_indexes,
    const int* __restrict__ frame,
    const int* __restrict__ pos,
    float* __restrict__ out)
{
    const int t = threadIdx.x;
    const int lane = t & 63;
    if (lane >= C_ / 4) return;
    const int base = (blockIdx.x << 3) + (t >> 6);   // rows base..base+7, this thread: base, base+4

    #pragma unroll
    for (int h = 0; h < 2; h++) {
        const int r = base + h * 4;
        const int b = r >> 8;
        const int l = r & 255;

        const int hi  = __ldg(&head_indexes[r]);
        const int p   = __ldg(&pos[b]);
        const int rel = l - p + 256;
        const int fk  = (l == p) ? __ldg(&frame[b]) : 0;

        const float4 s = ((const float4*)(g_SW  + ((size_t)b * L_ + hi) * C_))[lane];
        const float4 q = ((const float4*)(g_PEW + (size_t)rel * C_))[lane];
        const float4 f = ((const float4*)(g_CEW + (size_t)fk  * C_))[lane];

        float4 o;
        o.x = s.x + q.x + f.x;
        o.y = s.y + q.y + f.y;
        o.z = s.z + q.z + f.z;
        o.w = s.w + q.w + f.w;
        ((float4*)(out + (size_t)r * C_))[lane] = o;
    }
}

extern "C" void kernel_launch(void* const* d_in, const int* in_sizes, int n_in,
                              void* d_out, int out_size)
{
    const float* seq   = (const float*)d_in[0];
    const float* pe    = (const float*)d_in[1];
    const float* ce    = (const float*)d_in[2];
    const float* W     = (const float*)d_in[3];
    const float* bias  = (const float*)d_in[4];
    const int*   hidx  = (const int*)  d_in[5];
    const int*   frame = (const int*)  d_in[6];
    const int*   pos   = (const int*)  d_in[7];
    float* out = (float*)d_out;

    float *dSW, *dPEW, *dCEW;
    cudaGetSymbolAddress((void**)&dSW,  g_SW);
    cudaGetSymbolAddress((void**)&dPEW, g_PEW);
    cudaGetSymbolAddress((void**)&dCEW, g_CEW);

    static int init_done = 0;
    if (!init_done) {
        cudaFuncSetAttribute(tfgemm_fused,
                             cudaFuncAttributeMaxDynamicSharedMemorySize, SMEM_TOT);
        init_done = 1;
    }

    // 1) prepack W -> tf32 smem tile images (BK=64 layout)
    prepack_W<<<450, 256>>>(W);

    // 2) fused triple GEMM: full-N block tile, BK=64, single wave of 135 CTAs
    tfgemm_fused<<<NBLK_MAIN + NBLK_PE + NBLK_CE, 256, SMEM_TOT>>>(
        seq, pe, ce, bias, dSW, dPEW, dCEW);

    // 3) gather + add epilogue (2-row shape, proven)
    epilogue_kernel<<<(B_ * L_) / 8, 256>>>(hidx, frame, pos, out);
}

// round 16
// speedup vs baseline: 1.6517x; 1.3578x over previous
#include <cuda_runtime.h>
#include <cuda_fp16.h>
#include <cstdint>

// Problem constants
#define B_   64
#define L_   256
#define D_   768
#define C_   200
#define WLD  2304
#define PE_ROWS 513
#define CE_ROWS 201

// GEMM tiling: 128 x 200 block tile, BK=64 halfs, fp16 m16n8k16
#define BM 128
#define BK 64
#define KT 12                  // 768/64
#define P32 36                 // smem row pitch in 32-bit words (32 data + 4 pad; conflict-free)
#define NBLK_MAIN 128
#define NBLK_PE   5
#define NBLK_CE   2

// smem word offsets: A tile 128*36=4608 w, B tile 200*36=7200 w (same as proven R14 map)
#define AW0 0
#define AW1 4608
#define BW0 9216
#define BW1 16416
#define SMEM_TOT 94464         // 23616 words * 4

#define IMGW 7200              // words per B image (200 rows x 36)

// Scratch (device globals — no allocation allowed)
__device__ float g_SW [B_ * L_ * C_];
__device__ float g_PEW[PE_ROWS * C_];
__device__ float g_CEW[CE_ROWS * C_];
// W prepacked as fp16 images: [seg(3)][kt(12)], 200 x P32 words (~1.04 MB)
__device__ __align__(16) uint32_t g_Wimg[3 * KT * IMGW];

// ---------------- helpers ----------------
__device__ __forceinline__ uint32_t smem_u32(const void* p) {
    uint32_t a;
    asm("{ .reg .u64 t; cvta.to.shared.u64 t, %1; cvt.u32.u64 %0, t; }" : "=r"(a) : "l"(p));
    return a;
}
__device__ __forceinline__ uint32_t h2pack(float x, float y) {
    __half2 h = __float22half2_rn(make_float2(x, y));
    return *reinterpret_cast<uint32_t*>(&h);
}
__device__ __forceinline__ void mma_f16(float* d, const uint32_t* a, const uint32_t* b) {
    asm volatile(
        "mma.sync.aligned.m16n8k16.row.col.f32.f16.f16.f32 "
        "{%0,%1,%2,%3}, {%4,%5,%6,%7}, {%8,%9}, {%0,%1,%2,%3};\n"
        : "+f"(d[0]), "+f"(d[1]), "+f"(d[2]), "+f"(d[3])
        : "r"(a[0]), "r"(a[1]), "r"(a[2]), "r"(a[3]), "r"(b[0]), "r"(b[1]));
}
#define CP_ASYNC16(dst, src) \
    asm volatile("cp.async.cg.shared.global [%0], [%1], 16;" :: "r"(dst), "l"(src))
#define CP_COMMIT()  asm volatile("cp.async.commit_group;" ::: "memory")
#define CP_WAIT0()   asm volatile("cp.async.wait_group 0;" ::: "memory")

// ---------------- prepack W -> fp16 smem-image tiles ----------------
// 36 images x 200 rows x 9 16B-units = 64800 units; 1 unit/thread (grid 254)
__global__ __launch_bounds__(256) void prepack_W(const float* __restrict__ W) {
    const int u = blockIdx.x * 256 + threadIdx.x;
    if (u >= 36 * 1800) return;
    const int image = u / 1800;        // seg*KT + kt
    const int rem   = u % 1800;
    const int row   = rem / 9;         // 0..199 (= class)
    const int u9    = rem % 9;         // 8 data units + 1 pad unit per 144B row

    const int seg = image / KT;
    const int kt  = image % KT;

    uint4 o = make_uint4(0, 0, 0, 0);
    if (u9 < 8) {
        const float* src = W + (size_t)row * WLD + seg * D_ + kt * BK + u9 * 8;
        float4 v0 = *(const float4*)(src);
        float4 v1 = *(const float4*)(src + 4);
        o = make_uint4(h2pack(v0.x, v0.y), h2pack(v0.z, v0.w),
                       h2pack(v1.x, v1.y), h2pack(v1.z, v1.w));
    }
    *(uint4*)(g_Wimg + (size_t)image * IMGW + row * P32 + u9 * 4) = o;
}

// ---------------- fused triple GEMM (fp16 m16n8k16, full-N block tile) ----------------
__global__ __launch_bounds__(256, 1) void hgemm_fused(
    const float* __restrict__ A0,
    const float* __restrict__ A1,
    const float* __restrict__ A2,
    const float* __restrict__ bias,
    float* __restrict__ C0,
    float* __restrict__ C1,
    float* __restrict__ C2)
{
    // segment select
    int bx = blockIdx.x;
    const float* A;
    float* C;
    int M, seg;
    if (bx < NBLK_MAIN)                { A = A0; C = C0; M = B_ * L_; seg = 0; }
    else if (bx < NBLK_MAIN + NBLK_PE) { A = A1; C = C1; M = PE_ROWS; seg = 1; bx -= NBLK_MAIN; }
    else                               { A = A2; C = C2; M = CE_ROWS; seg = 2; bx -= NBLK_MAIN + NBLK_PE; }
    const int m0 = bx * BM;

    extern __shared__ __align__(16) char smem[];
    uint32_t* SW32 = (uint32_t*)smem;
    const uint32_t sb = smem_u32(smem);

    const int tid  = threadIdx.x;
    const int lane = tid & 31;
    const int wid  = tid >> 5;
    const int warp_m = wid & 3;    // 4 M-warps (32 rows each)
    const int warp_n = wid >> 2;   // 2 N-warp columns
    const int g   = lane >> 2;     // 0..7
    const int tig = lane & 3;      // 0..3

    // 25 n-tiles split 13/12 across warp_n (warp-uniform); SMSPs balanced
    const int nt0 = (warp_n == 0) ? 0 : 13;
    const int ntc = (warp_n == 0) ? 13 : 12;

    // A staging geometry: 256 threads cover 128x64-half tile (1024 uint4), 4/thread
    const int st_row = tid >> 3;   // 0..31, +32 per i
    const int st_uc  = tid & 7;    // uint4 column 0..7 (covers 8 halfs each)

    const uint32_t* wimg = g_Wimg + (size_t)(seg * KT) * IMGW;

    float acc[2][13][4];
    #pragma unroll
    for (int mt = 0; mt < 2; mt++)
        #pragma unroll
        for (int nt = 0; nt < 13; nt++)
            #pragma unroll
            for (int r = 0; r < 4; r++) acc[mt][nt][r] = 0.f;

    auto stageB = [&](int kt, int bwoff) {
        const uint32_t dstb = sb + (uint32_t)bwoff * 4;
        const char* src = (const char*)(wimg + (size_t)kt * IMGW);
        #pragma unroll
        for (int i = 0; i < 8; i++) {
            const int idx = tid + i * 256;
            if (idx < 1800)
                CP_ASYNC16(dstb + (uint32_t)idx * 16, src + (size_t)idx * 16);
        }
        CP_COMMIT();
    };
    // load 8 float4 (= 8 floats x 4 rows) per thread
    auto loadA = [&](int kt, float4* av) {
        #pragma unroll
        for (int i = 0; i < 4; i++) {
            const int row = st_row + i * 32;
            av[2*i]   = make_float4(0.f, 0.f, 0.f, 0.f);
            av[2*i+1] = make_float4(0.f, 0.f, 0.f, 0.f);
            if (m0 + row < M) {
                const float* src = A + (size_t)(m0 + row) * D_ + kt * BK + st_uc * 8;
                av[2*i]   = *(const float4*)(src);
                av[2*i+1] = *(const float4*)(src + 4);
            }
        }
    };
    auto storeA = [&](const float4* av, int awoff) {
        #pragma unroll
        for (int i = 0; i < 4; i++) {
            const int row = st_row + i * 32;
            const float4 v0 = av[2*i], v1 = av[2*i+1];
            uint4 o = make_uint4(h2pack(v0.x, v0.y), h2pack(v0.z, v0.w),
                                 h2pack(v1.x, v1.y), h2pack(v1.z, v1.w));
            *(uint4*)(SW32 + awoff + row * P32 + st_uc * 4) = o;
        }
    };

    // prologue
    float4 av[8];
    stageB(0, BW0);
    loadA(0, av);
    storeA(av, AW0);
    CP_WAIT0();
    __syncthreads();

    #pragma unroll 1
    for (int kt = 0; kt < KT; kt++) {
        const int b = kt & 1;
        const bool more = (kt + 1) < KT;
        if (more) {                    // issue next-tile loads BEFORE compute
            stageB(kt + 1, b ? BW0 : BW1);
            loadA(kt + 1, av);
        }

        const uint32_t* As = SW32 + (b ? AW1 : AW0);
        const uint32_t* Bs = SW32 + (b ? BW1 : BW0);

        #pragma unroll
        for (int ks = 0; ks < 4; ks++) {          // 4 k16 steps per BK=64
            const int k0 = ks * 8 + tig;           // word index within row
            uint32_t bf[13][2];
            #pragma unroll
            for (int nt = 0; nt < 13; nt++) {
                if (nt < ntc) {
                    const int naddr = ((nt0 + nt) * 8 + g) * P32 + k0;
                    bf[nt][0] = Bs[naddr];
                    bf[nt][1] = Bs[naddr + 4];
                }
            }
            #pragma unroll
            for (int mt = 0; mt < 2; mt++) {
                const int maddr = (warp_m * 32 + mt * 16 + g) * P32 + k0;
                uint32_t a[4];
                a[0] = As[maddr];                   // row g,   k 2tig..2tig+1
                a[1] = As[maddr + 8 * P32];         // row g+8, same k
                a[2] = As[maddr + 4];               // row g,   k +8
                a[3] = As[maddr + 8 * P32 + 4];     // row g+8, k +8
                #pragma unroll
                for (int nt = 0; nt < 13; nt++)
                    if (nt < ntc)
                        mma_f16(acc[mt][nt], a, bf[nt]);
            }
        }

        if (more) {
            storeA(av, b ? AW0 : AW1);   // convert+store AFTER compute (latency hidden)
            CP_WAIT0();
            __syncthreads();
        }
    }

    // ---- store (bias folded into CEW segment) ----
    #pragma unroll
    for (int mt = 0; mt < 2; mt++) {
        const int m_g = m0 + warp_m * 32 + mt * 16 + g;
        #pragma unroll
        for (int nt = 0; nt < 13; nt++) {
            if (nt < ntc) {
                const int n_g = (nt0 + nt) * 8 + 2 * tig;
                if (n_g < C_) {
                    float b0 = 0.f, b1 = 0.f;
                    if (seg == 2) { b0 = bias[n_g]; b1 = bias[n_g + 1]; }
                    if (m_g < M)
                        *(float2*)(C + (size_t)m_g * C_ + n_g) =
                            make_float2(acc[mt][nt][0] + b0, acc[mt][nt][1] + b1);
                    if (m_g + 8 < M)
                        *(float2*)(C + (size_t)(m_g + 8) * C_ + n_g) =
                            make_float2(acc[mt][nt][2] + b0, acc[mt][nt][3] + b1);
                }
            }
        }
    }
}

// ---------------- gather + add epilogue (2 rows per thread, PROVEN shape) ----------------
__global__ __launch_bounds__(256) void epilogue_kernel(
    const int* __restrict__ head_indexes,
    const int* __restrict__ frame,
    const int* __restrict__ pos,
    float* __restrict__ out)
{
    const int t = threadIdx.x;
    const int lane = t & 63;
    if (lane >= C_ / 4) return;
    const int base = (blockIdx.x << 3) + (t >> 6);   // rows base..base+7, this thread: base, base+4

    #pragma unroll
    for (int h = 0; h < 2; h++) {
        const int r = base + h * 4;
        const int b = r >> 8;
        const int l = r & 255;

        const int hi  = __ldg(&head_indexes[r]);
        const int p   = __ldg(&pos[b]);
        const int rel = l - p + 256;
        const int fk  = (l == p) ? __ldg(&frame[b]) : 0;

        const float4 s = ((const float4*)(g_SW  + ((size_t)b * L_ + hi) * C_))[lane];
        const float4 q = ((const float4*)(g_PEW + (size_t)rel * C_))[lane];
        const float4 f = ((const float4*)(g_CEW + (size_t)fk  * C_))[lane];

        float4 o;
        o.x = s.x + q.x + f.x;
        o.y = s.y + q.y + f.y;
        o.z = s.z + q.z + f.z;
        o.w = s.w + q.w + f.w;
        ((float4*)(out + (size_t)r * C_))[lane] = o;
    }
}

extern "C" void kernel_launch(void* const* d_in, const int* in_sizes, int n_in,
                              void* d_out, int out_size)
{
    const float* seq   = (const float*)d_in[0];
    const float* pe    = (const float*)d_in[1];
    const float* ce    = (const float*)d_in[2];
    const float* W     = (const float*)d_in[3];
    const float* bias  = (const float*)d_in[4];
    const int*   hidx  = (const int*)  d_in[5];
    const int*   frame = (const int*)  d_in[6];
    const int*   pos   = (const int*)  d_in[7];
    float* out = (float*)d_out;

    float *dSW, *dPEW, *dCEW;
    cudaGetSymbolAddress((void**)&dSW,  g_SW);
    cudaGetSymbolAddress((void**)&dPEW, g_PEW);
    cudaGetSymbolAddress((void**)&dCEW, g_CEW);

    static int init_done = 0;
    if (!init_done) {
        cudaFuncSetAttribute(hgemm_fused,
                             cudaFuncAttributeMaxDynamicSharedMemorySize, SMEM_TOT);
        init_done = 1;
    }

    // 1) prepack W -> fp16 smem tile images (~1 MB)
    prepack_W<<<254, 256>>>(W);

    // 2) fused triple GEMM: fp16 m16n8k16, full-N block tile, single wave
    hgemm_fused<<<NBLK_MAIN + NBLK_PE + NBLK_CE, 256, SMEM_TOT>>>(
        seq, pe, ce, bias, dSW, dPEW, dCEW);

    // 3) gather + add epilogue (2-row shape, proven)
    epilogue_kernel<<<(B_ * L_) / 8, 256>>>(hidx, frame, pos, out);
}